// round 2
// baseline (speedup 1.0000x reference)
#include <cuda_runtime.h>
#include <math.h>
#include <stdint.h>

#define NN 50000
#define NE 800000
#define D  128
#define DE 16
#define G4 512   // 4*D gates

// ---------------- scratch (static device globals; no allocation) ----------------
__device__ __align__(16) float g_W[2 * D * D];        // evolving LSTM state (hs) per layer
__device__ __align__(16) float g_G0[2 * D * G4];      // precomputed Wih@x + b per layer
__device__ __align__(16) float g_WihT[2 * D * G4];    // transposed Wih for coalesced G0 GEMM
__device__ __align__(16) float g_ft[(size_t)NN * D];  // nf @ W
__device__ __align__(16) float g_feat[(size_t)NN * D];// layer-0 GAT output (post leaky)
__device__ __align__(16) float g_out[(size_t)NN * D]; // aggregation accumulator
__device__ float    g_sc[NE];      // edge score, then overwritten with exp
__device__ float    g_ssrc[NN];
__device__ float    g_sdst[NN];
__device__ float    g_den[NN];
__device__ unsigned g_mx[NN];      // ordered-int encoded segment max

// ordered-int encoding for float atomicMax
__device__ __forceinline__ unsigned fenc(float f) {
    unsigned u = __float_as_uint(f);
    return (u & 0x80000000u) ? ~u : (u | 0x80000000u);
}
__device__ __forceinline__ float fdec(unsigned e) {
    return (e & 0x80000000u) ? __uint_as_float(e ^ 0x80000000u) : __uint_as_float(~e);
}

// ---------------- LSTM ----------------

// transpose Wih (L,512,128) -> WihT (L,128,512) for coalesced reads in G0
__global__ void k_transpose_wih(const float* __restrict__ Wih) {
    int idx = blockIdx.x * 256 + threadIdx.x;
    if (idx >= 2 * G4 * D) return;
    int layer = idx / (G4 * D);
    int rem   = idx - layer * (G4 * D);
    int g = rem / D, k = rem % D;
    g_WihT[(size_t)layer * (D * G4) + k * G4 + g] = Wih[idx];
}

// G0[t][g] = b[g] + sum_k X[t][k] * Wih[g][k]   (X = W0 or current state)
__global__ void __launch_bounds__(512) k_lstm_g0(
    const float* __restrict__ Xext, int use_state,
    const float* __restrict__ bih, const float* __restrict__ bhh)
{
    int t = blockIdx.x, layer = blockIdx.y;
    int g = threadIdx.x;
    __shared__ float xs[D];
    const float* X = use_state ? (g_W + layer * D * D) : (Xext + layer * D * D);
    if (g < D) xs[g] = X[t * D + g];
    __syncthreads();
    const float* wt = g_WihT + (size_t)layer * (D * G4);
    float acc = bih[layer * G4 + g] + bhh[layer * G4 + g];
#pragma unroll 8
    for (int k = 0; k < D; k++)
        acc = fmaf(wt[k * G4 + g], xs[k], acc);
    g_G0[(size_t)(layer * D + t) * G4 + g] = acc;
}

// 128-step recurrence, one CTA per layer (grid=2). Whh: k[0:96) in smem
// (interleaved float4 layout, conflict-free), k[96:128) in registers.
__global__ void __launch_bounds__(512, 1) k_lstm_rec(const float* __restrict__ Whh)
{
    int layer = blockIdx.x;
    extern __shared__ float sh[];
    float4* wsm = (float4*)sh;           // 24*512 float4 = 192KB
    float*  hsm = sh + 24 * 512 * 4;     // 128 floats
    float*  gsm = hsm + 128;             // 512 floats
    int r = threadIdx.x;

    const float4* wrow = (const float4*)(Whh + (size_t)(layer * G4 + r) * D);
    float4 wr[8];
#pragma unroll
    for (int k4 = 0; k4 < 24; k4++) wsm[k4 * 512 + r] = wrow[k4];
#pragma unroll
    for (int i = 0; i < 8; i++) wr[i] = wrow[24 + i];
    if (r < D) hsm[r] = 0.f;
    float c = 0.f;
    const float* g0 = g_G0 + (size_t)layer * (D * G4);
    float* ws = g_W + layer * D * D;
    __syncthreads();

    for (int t = 0; t < D; t++) {
        float acc = g0[t * G4 + r];
        const float4* h4 = (const float4*)hsm;
#pragma unroll
        for (int k4 = 0; k4 < 24; k4++) {
            float4 w = wsm[k4 * 512 + r];
            float4 h = h4[k4];
            acc = fmaf(w.x, h.x, acc); acc = fmaf(w.y, h.y, acc);
            acc = fmaf(w.z, h.z, acc); acc = fmaf(w.w, h.w, acc);
        }
#pragma unroll
        for (int i = 0; i < 8; i++) {
            float4 w = wr[i]; float4 h = h4[24 + i];
            acc = fmaf(w.x, h.x, acc); acc = fmaf(w.y, h.y, acc);
            acc = fmaf(w.z, h.z, acc); acc = fmaf(w.w, h.w, acc);
        }
        // gate order: i, f, g, o ; g uses tanh, others sigmoid
        float a = (r >= 256 && r < 384) ? tanhf(acc) : (1.f / (1.f + expf(-acc)));
        gsm[r] = a;
        __syncthreads();
        if (r < D) {
            float iv = gsm[r], fv = gsm[r + 128], gv = gsm[r + 256], ov = gsm[r + 384];
            c = fmaf(fv, c, iv * gv);
            float h = ov * tanhf(c);
            hsm[r] = h;
            ws[t * D + r] = h;   // hs row t
        }
        __syncthreads();
    }
}

// ---------------- GAT ----------------

__global__ void k_init() {
    int idx = blockIdx.x * 256 + threadIdx.x;
    if (idx < NN * D) g_out[idx] = 0.f;
    if (idx < NN) { g_mx[idx] = 0u; g_den[idx] = 0.f; }
}

// ft = nf @ W ; s_src = nf @ a_src ; s_dst = nf @ a_dst. Warp-per-row, W in smem.
__global__ void __launch_bounds__(256) k_gat_gemm(
    const float* __restrict__ nf_ext, int layer, const float* __restrict__ a_w)
{
    extern __shared__ float sh[];
    float* Wsm  = sh;              // 128*128
    float* av   = sh + D * D;      // a_src[128], a_dst[128]
    float* xbuf = av + 2 * D;      // 8 warps * 128
    int tid = threadIdx.x;
    const float* Wg = g_W + layer * D * D;
    for (int i = tid; i < D * D; i += 256) Wsm[i] = Wg[i];
    const float* aw = a_w + layer * (2 * D + DE);
    if (tid < D) { av[tid] = aw[tid]; av[D + tid] = aw[D + DE + tid]; }
    __syncthreads();

    const float* nf = layer ? g_feat : nf_ext;
    int warp = tid >> 5, lane = tid & 31;
    int row = blockIdx.x * 8 + warp;
    if (row >= NN) return;

    float* xb = xbuf + warp * D;
    float4 x = ((const float4*)(nf + (size_t)row * D))[lane];
    ((float4*)xb)[lane] = x;
    __syncwarp();

    float ss = x.x * av[lane * 4] + x.y * av[lane * 4 + 1]
             + x.z * av[lane * 4 + 2] + x.w * av[lane * 4 + 3];
    float sd = x.x * av[D + lane * 4] + x.y * av[D + lane * 4 + 1]
             + x.z * av[D + lane * 4 + 2] + x.w * av[D + lane * 4 + 3];

    float4 acc = make_float4(0.f, 0.f, 0.f, 0.f);
    const float4* W4  = (const float4*)Wsm;
    const float4* xb4 = (const float4*)xb;
#pragma unroll 8
    for (int k4 = 0; k4 < 32; k4++) {
        float4 xk = xb4[k4];
        float4 w;
        w = W4[(k4 * 4 + 0) * 32 + lane];
        acc.x = fmaf(xk.x, w.x, acc.x); acc.y = fmaf(xk.x, w.y, acc.y);
        acc.z = fmaf(xk.x, w.z, acc.z); acc.w = fmaf(xk.x, w.w, acc.w);
        w = W4[(k4 * 4 + 1) * 32 + lane];
        acc.x = fmaf(xk.y, w.x, acc.x); acc.y = fmaf(xk.y, w.y, acc.y);
        acc.z = fmaf(xk.y, w.z, acc.z); acc.w = fmaf(xk.y, w.w, acc.w);
        w = W4[(k4 * 4 + 2) * 32 + lane];
        acc.x = fmaf(xk.z, w.x, acc.x); acc.y = fmaf(xk.z, w.y, acc.y);
        acc.z = fmaf(xk.z, w.z, acc.z); acc.w = fmaf(xk.z, w.w, acc.w);
        w = W4[(k4 * 4 + 3) * 32 + lane];
        acc.x = fmaf(xk.w, w.x, acc.x); acc.y = fmaf(xk.w, w.y, acc.y);
        acc.z = fmaf(xk.w, w.z, acc.z); acc.w = fmaf(xk.w, w.w, acc.w);
    }
    ((float4*)(g_ft + (size_t)row * D))[lane] = acc;

#pragma unroll
    for (int o = 16; o; o >>= 1) {
        ss += __shfl_down_sync(0xffffffffu, ss, o);
        sd += __shfl_down_sync(0xffffffffu, sd, o);
    }
    if (lane == 0) { g_ssrc[row] = ss; g_sdst[row] = sd; }
}

__global__ void __launch_bounds__(256) k_edge_score(
    const int* __restrict__ src, const int* __restrict__ dst,
    const float* __restrict__ ef, const float* __restrict__ a_w,
    int layer, int n_edges)
{
    int e = blockIdx.x * 256 + threadIdx.x;
    if (e >= n_edges) return;
    const float* ae = a_w + layer * (2 * D + DE) + D;
    int s = src[e], d = dst[e];
    const float4* ep = (const float4*)(ef + (size_t)e * DE);
    float sc = g_ssrc[s] + g_sdst[d];
#pragma unroll
    for (int i = 0; i < 4; i++) {
        float4 v = ep[i];
        sc += v.x * __ldg(ae + i * 4) + v.y * __ldg(ae + i * 4 + 1)
            + v.z * __ldg(ae + i * 4 + 2) + v.w * __ldg(ae + i * 4 + 3);
    }
    g_sc[e] = sc;
    atomicMax(&g_mx[d], fenc(sc));
}

__global__ void __launch_bounds__(256) k_edge_exp(const int* __restrict__ dst, int n_edges)
{
    int e = blockIdx.x * 256 + threadIdx.x;
    if (e >= n_edges) return;
    int d = dst[e];
    float ex = expf(g_sc[e] - fdec(g_mx[d]));
    g_sc[e] = ex;
    atomicAdd(&g_den[d], ex);
}

// one warp per edge: gather ft[src] (L2-resident), scale by alpha, v4 reduce into out[dst]
__global__ void __launch_bounds__(256) k_aggregate(
    const int* __restrict__ src, const int* __restrict__ dst, int n_edges)
{
    int gw = (blockIdx.x * 256 + threadIdx.x) >> 5;
    int lane = threadIdx.x & 31;
    if (gw >= n_edges) return;
    int s = 0, d = 0; float al = 0.f;
    if (lane == 0) {
        s = src[gw]; d = dst[gw];
        al = g_sc[gw] / g_den[d];
    }
    s  = __shfl_sync(0xffffffffu, s, 0);
    d  = __shfl_sync(0xffffffffu, d, 0);
    al = __shfl_sync(0xffffffffu, al, 0);
    float4 v = ((const float4*)(g_ft + (size_t)s * D))[lane];
    float* p = g_out + (size_t)d * D + lane * 4;
    asm volatile("red.global.add.v4.f32 [%0], {%1,%2,%3,%4};"
                 :: "l"(p), "f"(v.x * al), "f"(v.y * al), "f"(v.z * al), "f"(v.w * al)
                 : "memory");
}

__global__ void __launch_bounds__(256) k_finalize(float* __restrict__ dest_ext, int to_internal)
{
    int idx = blockIdx.x * 256 + threadIdx.x;
    if (idx >= NN * D) return;
    float v = g_out[idx];
    v = v >= 0.f ? v : 0.01f * v;   // leaky_relu, slope 0.01
    if (to_internal) g_feat[idx] = v;
    else dest_ext[idx] = v;
}

// ---------------- launch ----------------
extern "C" void kernel_launch(void* const* d_in, const int* in_sizes, int n_in,
                              void* d_out, int out_size)
{
    const int*   src     = (const int*)  d_in[0];
    const int*   dst     = (const int*)  d_in[1];
    const float* n_feats = (const float*)d_in[2];
    const float* e_feats = (const float*)d_in[3];
    const float* W0      = (const float*)d_in[4];
    const float* Wih     = (const float*)d_in[5];
    const float* Whh     = (const float*)d_in[6];
    const float* bih     = (const float*)d_in[7];
    const float* bhh     = (const float*)d_in[8];
    const float* a_w     = (const float*)d_in[9];

    int n_edges = in_sizes[0] / 3;        // 800000
    int n_nodes = in_sizes[2] / (3 * D);  // 50000

    int smem_rec  = (24 * 512 * 4 + 128 + 512) * (int)sizeof(float);   // ~194.5KB
    int smem_gemm = (D * D + 2 * D + 8 * D) * (int)sizeof(float);      // ~70.5KB
    cudaFuncSetAttribute(k_lstm_rec, cudaFuncAttributeMaxDynamicSharedMemorySize, smem_rec);
    cudaFuncSetAttribute(k_gat_gemm, cudaFuncAttributeMaxDynamicSharedMemorySize, smem_gemm);

    // only timestep j=2 matters for the output (feats never mix across j)
    const int*   src2 = src + 2 * n_edges;
    const int*   dst2 = dst + 2 * n_edges;
    const float* nf2  = n_feats + (size_t)2 * n_nodes * D;
    const float* ef2  = e_feats + (size_t)2 * n_edges * DE;

    // LSTM chains for both layers run concurrently (grid.y / grid.x = 2)
    k_transpose_wih<<<(2 * G4 * D + 255) / 256, 256>>>(Wih);
    for (int call = 0; call < 3; call++) {
        k_lstm_g0<<<dim3(D, 2), 512>>>(W0, call > 0, bih, bhh);
        k_lstm_rec<<<2, 512, smem_rec>>>(Whh);
    }

    for (int layer = 0; layer < 2; layer++) {
        k_init<<<(n_nodes * D + 255) / 256, 256>>>();
        k_gat_gemm<<<(n_nodes + 7) / 8, 256, smem_gemm>>>(nf2, layer, a_w);
        k_edge_score<<<(n_edges + 255) / 256, 256>>>(src2, dst2, ef2, a_w, layer, n_edges);
        k_edge_exp<<<(n_edges + 255) / 256, 256>>>(dst2, n_edges);
        k_aggregate<<<(n_edges * 32 + 255) / 256, 256>>>(src2, dst2, n_edges);
        k_finalize<<<(n_nodes * D + 255) / 256, 256>>>((float*)d_out, layer == 0);
    }
}

// round 3
// speedup vs baseline: 1.0428x; 1.0428x over previous
#include <cuda_runtime.h>
#include <math.h>
#include <stdint.h>

#define NN 50000
#define NE 800000
#define D  128
#define DE 16
#define G4 512   // 4*D gates

// ---------------- scratch (static device globals; no allocation) ----------------
__device__ __align__(16) float g_W[2 * D * D];        // evolving LSTM state (hs) per layer
__device__ __align__(16) float g_G0[2 * D * G4];      // precomputed Wih@x + b per layer
__device__ __align__(16) float g_WihT[2 * D * G4];    // transposed Wih for coalesced G0 GEMM
__device__ __align__(16) float g_ft[(size_t)NN * D];  // nf @ W
__device__ __align__(16) float g_feat[(size_t)NN * D];// layer-0 GAT output (post leaky)
__device__ __align__(16) float g_out[(size_t)NN * D]; // aggregation accumulator
__device__ float    g_sc[NE];      // edge score, then overwritten with exp
__device__ float    g_ssrc[NN];
__device__ float    g_sdst[NN];
__device__ float    g_den[NN];
__device__ unsigned g_mx[NN];      // ordered-int encoded segment max

// ordered-int encoding for float atomicMax
__device__ __forceinline__ unsigned fenc(float f) {
    unsigned u = __float_as_uint(f);
    return (u & 0x80000000u) ? ~u : (u | 0x80000000u);
}
__device__ __forceinline__ float fdec(unsigned e) {
    return (e & 0x80000000u) ? __uint_as_float(e ^ 0x80000000u) : __uint_as_float(~e);
}

// packed f32x2 FMA (sm_103a FFMA2) — PTX-only, ptxas won't auto-fuse
__device__ __forceinline__ unsigned long long fma2(
    unsigned long long a, unsigned long long b, unsigned long long c)
{
    unsigned long long d;
    asm("fma.rn.f32x2 %0, %1, %2, %3;" : "=l"(d) : "l"(a), "l"(b), "l"(c));
    return d;
}
__device__ __forceinline__ float hsum2(unsigned long long a) {
    return __uint_as_float((unsigned)a) + __uint_as_float((unsigned)(a >> 32));
}
__device__ __forceinline__ float tanh_fast(float x) {
    float r; asm("tanh.approx.f32 %0, %1;" : "=f"(r) : "f"(x)); return r;
}
__device__ __forceinline__ float sig_fast(float x) {
    return __fdividef(1.f, 1.f + __expf(-x));
}

// ---------------- LSTM ----------------

// transpose Wih (L,512,128) -> WihT (L,128,512) for coalesced reads in G0
__global__ void k_transpose_wih(const float* __restrict__ Wih) {
    int idx = blockIdx.x * 256 + threadIdx.x;
    if (idx >= 2 * G4 * D) return;
    int layer = idx / (G4 * D);
    int rem   = idx - layer * (G4 * D);
    int g = rem / D, k = rem % D;
    g_WihT[(size_t)layer * (D * G4) + k * G4 + g] = Wih[idx];
}

// G0[t][g] = b[g] + sum_k X[t][k] * Wih[g][k]   (X = W0 or current state)
// 4 independent accumulators to break the serial FMA chain (round-2 fix: issue=14%)
__global__ void __launch_bounds__(512) k_lstm_g0(
    const float* __restrict__ Xext, int use_state,
    const float* __restrict__ bih, const float* __restrict__ bhh)
{
    int t = blockIdx.x, layer = blockIdx.y;
    int g = threadIdx.x;
    __shared__ float xs[D];
    const float* X = use_state ? (g_W + layer * D * D) : (Xext + layer * D * D);
    if (g < D) xs[g] = X[t * D + g];
    __syncthreads();
    const float* wt = g_WihT + (size_t)layer * (D * G4) + g;
    float a0 = bih[layer * G4 + g] + bhh[layer * G4 + g];
    float a1 = 0.f, a2 = 0.f, a3 = 0.f;
#pragma unroll
    for (int k = 0; k < D; k += 4) {
        a0 = fmaf(wt[(k + 0) * G4], xs[k + 0], a0);
        a1 = fmaf(wt[(k + 1) * G4], xs[k + 1], a1);
        a2 = fmaf(wt[(k + 2) * G4], xs[k + 2], a2);
        a3 = fmaf(wt[(k + 3) * G4], xs[k + 3], a3);
    }
    g_G0[(size_t)(layer * D + t) * G4 + g] = (a0 + a1) + (a2 + a3);
}

// 128-step recurrence, one CTA of 1024 threads per layer (grid=2).
// thread = (half = tid>>9, row r = tid&511); each covers k in [half*64, half*64+64):
//   first 48 k's: W in registers (24 f32x2), last 16 k's: W in smem (conflict-free).
// Packed fma.rn.f32x2 throughout; cross-half reduce via smem partial[].
__global__ void __launch_bounds__(1024, 1) k_lstm_rec(const float* __restrict__ Whh)
{
    int layer = blockIdx.x;
    extern __shared__ float sh[];
    ulonglong2* wtail = (ulonglong2*)sh;                 // 8*512 u128 = 64KB
    float* hsm     = sh + 8 * 512 * 4;                   // 128 floats
    float* partial = hsm + 128;                          // 1024 floats

    int tid  = threadIdx.x;
    int half = tid >> 9;
    int r    = tid & 511;

    // load this thread's 64 W floats: 48 -> regs, 16 -> smem
    const ulonglong2* wrow =
        (const ulonglong2*)(Whh + ((size_t)(layer * G4 + r)) * D + half * 64);
    unsigned long long wreg[24];
#pragma unroll
    for (int j = 0; j < 12; j++) {
        ulonglong2 v = wrow[j];
        wreg[2 * j] = v.x; wreg[2 * j + 1] = v.y;
    }
#pragma unroll
    for (int j4 = 0; j4 < 4; j4++)
        wtail[(half * 4 + j4) * 512 + r] = wrow[12 + j4];

    if (tid < D) hsm[tid] = 0.f;
    float c = 0.f;
    const float* g0 = g_G0 + (size_t)layer * (D * G4);
    float* ws = g_W + layer * D * D;
    __syncthreads();

    const ulonglong2* h2 = (const ulonglong2*)(hsm + half * 64);
    const ulonglong2* wt_base = wtail + half * 4 * 512 + r;

    for (int t = 0; t < D; t++) {
        // prefetch g0 for the epilogue (hidden under the FMA phase)
        float q0, q1, q2, q3;
        if (tid < D) {
            const float* gp = g0 + t * G4 + tid;
            q0 = __ldg(gp); q1 = __ldg(gp + 128);
            q2 = __ldg(gp + 256); q3 = __ldg(gp + 384);
        }

        unsigned long long acc = 0ull;   // (+0.0f, +0.0f)
#pragma unroll
        for (int j = 0; j < 12; j++) {
            ulonglong2 hh = h2[j];
            acc = fma2(wreg[2 * j],     hh.x, acc);
            acc = fma2(wreg[2 * j + 1], hh.y, acc);
        }
#pragma unroll
        for (int j4 = 0; j4 < 4; j4++) {
            ulonglong2 w = wt_base[j4 * 512];
            ulonglong2 hh = h2[12 + j4];
            acc = fma2(w.x, hh.x, acc);
            acc = fma2(w.y, hh.y, acc);
        }
        partial[tid] = hsum2(acc);
        __syncthreads();

        if (tid < D) {
            float gi = q0 + partial[tid]       + partial[tid + 512];
            float gf = q1 + partial[tid + 128] + partial[tid + 640];
            float gg = q2 + partial[tid + 256] + partial[tid + 768];
            float go = q3 + partial[tid + 384] + partial[tid + 896];
            float iv = sig_fast(gi), fv = sig_fast(gf);
            float gv = tanh_fast(gg), ov = sig_fast(go);
            c = fmaf(fv, c, iv * gv);
            float h = ov * tanh_fast(c);
            hsm[tid] = h;
            ws[t * D + tid] = h;
        }
        __syncthreads();
    }
}

// ---------------- GAT ----------------

__global__ void k_init() {
    int idx = blockIdx.x * 256 + threadIdx.x;
    if (idx < NN * D / 4)
        ((float4*)g_out)[idx] = make_float4(0.f, 0.f, 0.f, 0.f);
    if (idx < NN) { g_mx[idx] = 0u; g_den[idx] = 0.f; }
}

// ft = nf @ W ; s_src = nf @ a_src ; s_dst = nf @ a_dst. Warp-per-row, W in smem.
__global__ void __launch_bounds__(256) k_gat_gemm(
    const float* __restrict__ nf_ext, int layer, const float* __restrict__ a_w)
{
    extern __shared__ float sh[];
    float* Wsm  = sh;              // 128*128
    float* av   = sh + D * D;      // a_src[128], a_dst[128]
    float* xbuf = av + 2 * D;      // 8 warps * 128
    int tid = threadIdx.x;
    const float* Wg = g_W + layer * D * D;
    for (int i = tid; i < D * D; i += 256) Wsm[i] = Wg[i];
    const float* aw = a_w + layer * (2 * D + DE);
    if (tid < D) { av[tid] = aw[tid]; av[D + tid] = aw[D + DE + tid]; }
    __syncthreads();

    const float* nf = layer ? g_feat : nf_ext;
    int warp = tid >> 5, lane = tid & 31;
    int row = blockIdx.x * 8 + warp;
    if (row >= NN) return;

    float* xb = xbuf + warp * D;
    float4 x = ((const float4*)(nf + (size_t)row * D))[lane];
    ((float4*)xb)[lane] = x;
    __syncwarp();

    float ss = x.x * av[lane * 4] + x.y * av[lane * 4 + 1]
             + x.z * av[lane * 4 + 2] + x.w * av[lane * 4 + 3];
    float sd = x.x * av[D + lane * 4] + x.y * av[D + lane * 4 + 1]
             + x.z * av[D + lane * 4 + 2] + x.w * av[D + lane * 4 + 3];

    float4 acc = make_float4(0.f, 0.f, 0.f, 0.f);
    const float4* W4  = (const float4*)Wsm;
    const float4* xb4 = (const float4*)xb;
#pragma unroll 8
    for (int k4 = 0; k4 < 32; k4++) {
        float4 xk = xb4[k4];
        float4 w;
        w = W4[(k4 * 4 + 0) * 32 + lane];
        acc.x = fmaf(xk.x, w.x, acc.x); acc.y = fmaf(xk.x, w.y, acc.y);
        acc.z = fmaf(xk.x, w.z, acc.z); acc.w = fmaf(xk.x, w.w, acc.w);
        w = W4[(k4 * 4 + 1) * 32 + lane];
        acc.x = fmaf(xk.y, w.x, acc.x); acc.y = fmaf(xk.y, w.y, acc.y);
        acc.z = fmaf(xk.y, w.z, acc.z); acc.w = fmaf(xk.y, w.w, acc.w);
        w = W4[(k4 * 4 + 2) * 32 + lane];
        acc.x = fmaf(xk.z, w.x, acc.x); acc.y = fmaf(xk.z, w.y, acc.y);
        acc.z = fmaf(xk.z, w.z, acc.z); acc.w = fmaf(xk.z, w.w, acc.w);
        w = W4[(k4 * 4 + 3) * 32 + lane];
        acc.x = fmaf(xk.w, w.x, acc.x); acc.y = fmaf(xk.w, w.y, acc.y);
        acc.z = fmaf(xk.w, w.z, acc.z); acc.w = fmaf(xk.w, w.w, acc.w);
    }
    ((float4*)(g_ft + (size_t)row * D))[lane] = acc;

#pragma unroll
    for (int o = 16; o; o >>= 1) {
        ss += __shfl_down_sync(0xffffffffu, ss, o);
        sd += __shfl_down_sync(0xffffffffu, sd, o);
    }
    if (lane == 0) { g_ssrc[row] = ss; g_sdst[row] = sd; }
}

__global__ void __launch_bounds__(256) k_edge_score(
    const int* __restrict__ src, const int* __restrict__ dst,
    const float* __restrict__ ef, const float* __restrict__ a_w,
    int layer, int n_edges)
{
    int e = blockIdx.x * 256 + threadIdx.x;
    if (e >= n_edges) return;
    const float* ae = a_w + layer * (2 * D + DE) + D;
    int s = src[e], d = dst[e];
    const float4* ep = (const float4*)(ef + (size_t)e * DE);
    float sc = g_ssrc[s] + g_sdst[d];
#pragma unroll
    for (int i = 0; i < 4; i++) {
        float4 v = ep[i];
        sc += v.x * __ldg(ae + i * 4) + v.y * __ldg(ae + i * 4 + 1)
            + v.z * __ldg(ae + i * 4 + 2) + v.w * __ldg(ae + i * 4 + 3);
    }
    g_sc[e] = sc;
    atomicMax(&g_mx[d], fenc(sc));
}

__global__ void __launch_bounds__(256) k_edge_exp(const int* __restrict__ dst, int n_edges)
{
    int e = blockIdx.x * 256 + threadIdx.x;
    if (e >= n_edges) return;
    int d = dst[e];
    float ex = __expf(g_sc[e] - fdec(g_mx[d]));
    g_sc[e] = ex;
    atomicAdd(&g_den[d], ex);
}

// one warp per edge: gather ft[src] (L2-resident), scale by alpha, v4 reduce into out[dst]
__global__ void __launch_bounds__(256) k_aggregate(
    const int* __restrict__ src, const int* __restrict__ dst, int n_edges)
{
    int gw = (blockIdx.x * 256 + threadIdx.x) >> 5;
    int lane = threadIdx.x & 31;
    if (gw >= n_edges) return;
    int s = 0, d = 0; float al = 0.f;
    if (lane == 0) {
        s = src[gw]; d = dst[gw];
        al = g_sc[gw] / g_den[d];
    }
    s  = __shfl_sync(0xffffffffu, s, 0);
    d  = __shfl_sync(0xffffffffu, d, 0);
    al = __shfl_sync(0xffffffffu, al, 0);
    float4 v = ((const float4*)(g_ft + (size_t)s * D))[lane];
    float* p = g_out + (size_t)d * D + lane * 4;
    asm volatile("red.global.add.v4.f32 [%0], {%1,%2,%3,%4};"
                 :: "l"(p), "f"(v.x * al), "f"(v.y * al), "f"(v.z * al), "f"(v.w * al)
                 : "memory");
}

__global__ void __launch_bounds__(256) k_finalize(float* __restrict__ dest_ext, int to_internal)
{
    int idx = blockIdx.x * 256 + threadIdx.x;
    if (idx >= NN * D) return;
    float v = g_out[idx];
    v = v >= 0.f ? v : 0.01f * v;   // leaky_relu, slope 0.01
    if (to_internal) g_feat[idx] = v;
    else dest_ext[idx] = v;
}

// ---------------- launch ----------------
extern "C" void kernel_launch(void* const* d_in, const int* in_sizes, int n_in,
                              void* d_out, int out_size)
{
    const int*   src     = (const int*)  d_in[0];
    const int*   dst     = (const int*)  d_in[1];
    const float* n_feats = (const float*)d_in[2];
    const float* e_feats = (const float*)d_in[3];
    const float* W0      = (const float*)d_in[4];
    const float* Wih     = (const float*)d_in[5];
    const float* Whh     = (const float*)d_in[6];
    const float* bih     = (const float*)d_in[7];
    const float* bhh     = (const float*)d_in[8];
    const float* a_w     = (const float*)d_in[9];

    int n_edges = in_sizes[0] / 3;        // 800000
    int n_nodes = in_sizes[2] / (3 * D);  // 50000

    int smem_rec  = (8 * 512 * 4 + 128 + 1024) * (int)sizeof(float);   // ~69.1KB
    int smem_gemm = (D * D + 2 * D + 8 * D) * (int)sizeof(float);      // ~70.5KB
    cudaFuncSetAttribute(k_lstm_rec, cudaFuncAttributeMaxDynamicSharedMemorySize, smem_rec);
    cudaFuncSetAttribute(k_gat_gemm, cudaFuncAttributeMaxDynamicSharedMemorySize, smem_gemm);

    // only timestep j=2 matters for the output (feats never mix across j)
    const int*   src2 = src + 2 * n_edges;
    const int*   dst2 = dst + 2 * n_edges;
    const float* nf2  = n_feats + (size_t)2 * n_nodes * D;
    const float* ef2  = e_feats + (size_t)2 * n_edges * DE;

    // LSTM chains for both layers run concurrently (grid.y / grid.x = 2)
    k_transpose_wih<<<(2 * G4 * D + 255) / 256, 256>>>(Wih);
    for (int call = 0; call < 3; call++) {
        k_lstm_g0<<<dim3(D, 2), 512>>>(W0, call > 0, bih, bhh);
        k_lstm_rec<<<2, 1024, smem_rec>>>(Whh);
    }

    for (int layer = 0; layer < 2; layer++) {
        k_init<<<(n_nodes * D / 4 + 255) / 256, 256>>>();
        k_gat_gemm<<<(n_nodes + 7) / 8, 256, smem_gemm>>>(nf2, layer, a_w);
        k_edge_score<<<(n_edges + 255) / 256, 256>>>(src2, dst2, ef2, a_w, layer, n_edges);
        k_edge_exp<<<(n_edges + 255) / 256, 256>>>(dst2, n_edges);
        k_aggregate<<<(n_edges * 32 + 255) / 256, 256>>>(src2, dst2, n_edges);
        k_finalize<<<(n_nodes * D + 255) / 256, 256>>>((float*)d_out, layer == 0);
    }
}

// round 5
// speedup vs baseline: 1.1117x; 1.0660x over previous
#include <cuda_runtime.h>
#include <math.h>
#include <stdint.h>

#define NN 50000
#define NE 800000
#define D  128
#define DE 16
#define G4 512   // 4*D gates

// ---------------- scratch (static device globals; no allocation) ----------------
__device__ __align__(16) float g_W[2 * D * D];        // evolving LSTM state (hs) per layer
__device__ __align__(16) float g_G0[2 * D * G4];      // precomputed Wih@x + b per layer
__device__ __align__(16) float g_WihT[2 * D * G4];    // transposed Wih for coalesced G0 GEMM
__device__ __align__(16) float g_ft[(size_t)NN * D];  // nf @ W
__device__ __align__(16) float g_feat[(size_t)NN * D];// layer-0 GAT output (post leaky)
__device__ float g_sc[NE];        // edge score (original edge order)
__device__ float g_ssrc[NN];
__device__ float g_sdst[NN];
// ---- dst-sorted edge structure (built once; graph identical across layers) ----
__device__ int g_cnt[NN + 1];     // counts -> exclusive offsets (in place)
__device__ int g_cur[NN];         // scatter cursors
__device__ int g_eid[NE];         // sorted position -> original edge id
__device__ int g_ssorted[NE];     // sorted position -> src node

// packed f32x2 FMA (sm_103a FFMA2) — PTX-only, ptxas won't auto-fuse
__device__ __forceinline__ unsigned long long fma2(
    unsigned long long a, unsigned long long b, unsigned long long c)
{
    unsigned long long d;
    asm("fma.rn.f32x2 %0, %1, %2, %3;" : "=l"(d) : "l"(a), "l"(b), "l"(c));
    return d;
}
__device__ __forceinline__ float hsum2(unsigned long long a) {
    return __uint_as_float((unsigned)a) + __uint_as_float((unsigned)(a >> 32));
}
__device__ __forceinline__ float tanh_fast(float x) {
    float r; asm("tanh.approx.f32 %0, %1;" : "=f"(r) : "f"(x)); return r;
}
__device__ __forceinline__ float sig_fast(float x) {
    return __fdividef(1.f, 1.f + __expf(-x));
}

// ---------------- edge sort (once) ----------------

__global__ void k_zero_cnt() {
    int idx = blockIdx.x * 256 + threadIdx.x;
    if (idx <= NN) g_cnt[idx] = 0;
}

__global__ void k_hist(const int* __restrict__ dst) {
    int e = blockIdx.x * 256 + threadIdx.x;
    if (e < NE) atomicAdd(&g_cnt[dst[e]], 1);
}

// single-CTA exclusive scan over 50k counts; writes offsets into g_cnt and g_cur
__global__ void __launch_bounds__(1024) k_scan() {
    const int CH = 49;                     // 1024*49 = 50176 >= NN
    int tid = threadIdx.x;
    int lane = tid & 31, wid = tid >> 5;
    int base = tid * CH;
    int s = 0;
    for (int i = 0; i < CH; i++) {
        int j = base + i;
        if (j < NN) s += g_cnt[j];
    }
    // block-wide inclusive scan of s
    __shared__ int wsum[32];
    int v = s;
#pragma unroll
    for (int o = 1; o < 32; o <<= 1) {
        int t = __shfl_up_sync(0xffffffffu, v, o);
        if (lane >= o) v += t;
    }
    if (lane == 31) wsum[wid] = v;
    __syncthreads();
    if (wid == 0) {
        int w = wsum[lane];
#pragma unroll
        for (int o = 1; o < 32; o <<= 1) {
            int t = __shfl_up_sync(0xffffffffu, w, o);
            if (lane >= o) w += t;
        }
        wsum[lane] = w;
    }
    __syncthreads();
    int run = v - s + (wid ? wsum[wid - 1] : 0);   // exclusive prefix
    for (int i = 0; i < CH; i++) {
        int j = base + i;
        if (j < NN) {
            int c = g_cnt[j];
            g_cnt[j] = run;
            g_cur[j] = run;
            run += c;
        }
    }
    if (tid == 1023) g_cnt[NN] = NE;
}

__global__ void k_scatter(const int* __restrict__ src, const int* __restrict__ dst) {
    int e = blockIdx.x * 256 + threadIdx.x;
    if (e >= NE) return;
    int d = dst[e];
    int pos = atomicAdd(&g_cur[d], 1);
    g_eid[pos] = e;
    g_ssorted[pos] = src[e];
}

// ---------------- LSTM ----------------

// transpose Wih (L,512,128) -> WihT (L,128,512) for coalesced reads in G0
__global__ void k_transpose_wih(const float* __restrict__ Wih) {
    int idx = blockIdx.x * 256 + threadIdx.x;
    if (idx >= 2 * G4 * D) return;
    int layer = idx / (G4 * D);
    int rem   = idx - layer * (G4 * D);
    int g = rem / D, k = rem % D;
    g_WihT[(size_t)layer * (D * G4) + k * G4 + g] = Wih[idx];
}

// G0[t][g] = b[g] + sum_k X[t][k] * Wih[g][k]   (X = W0 or current state)
__global__ void __launch_bounds__(512) k_lstm_g0(
    const float* __restrict__ Xext, int use_state,
    const float* __restrict__ bih, const float* __restrict__ bhh)
{
    int t = blockIdx.x, layer = blockIdx.y;
    int g = threadIdx.x;
    __shared__ float xs[D];
    const float* X = use_state ? (g_W + layer * D * D) : (Xext + layer * D * D);
    if (g < D) xs[g] = X[t * D + g];
    __syncthreads();
    const float* wt = g_WihT + (size_t)layer * (D * G4) + g;
    float a0 = bih[layer * G4 + g] + bhh[layer * G4 + g];
    float a1 = 0.f, a2 = 0.f, a3 = 0.f;
#pragma unroll
    for (int k = 0; k < D; k += 4) {
        a0 = fmaf(wt[(k + 0) * G4], xs[k + 0], a0);
        a1 = fmaf(wt[(k + 1) * G4], xs[k + 1], a1);
        a2 = fmaf(wt[(k + 2) * G4], xs[k + 2], a2);
        a3 = fmaf(wt[(k + 3) * G4], xs[k + 3], a3);
    }
    g_G0[(size_t)(layer * D + t) * G4 + g] = (a0 + a1) + (a2 + a3);
}

// 128-step recurrence, one CTA of 1024 threads per layer (grid=2).
__global__ void __launch_bounds__(1024, 1) k_lstm_rec(const float* __restrict__ Whh)
{
    int layer = blockIdx.x;
    extern __shared__ float sh[];
    ulonglong2* wtail = (ulonglong2*)sh;                 // 8*512 u128 = 64KB
    float* hsm     = sh + 8 * 512 * 4;                   // 128 floats
    float* partial = hsm + 128;                          // 1024 floats

    int tid  = threadIdx.x;
    int half = tid >> 9;
    int r    = tid & 511;

    const ulonglong2* wrow =
        (const ulonglong2*)(Whh + ((size_t)(layer * G4 + r)) * D + half * 64);
    unsigned long long wreg[24];
#pragma unroll
    for (int j = 0; j < 12; j++) {
        ulonglong2 v = wrow[j];
        wreg[2 * j] = v.x; wreg[2 * j + 1] = v.y;
    }
#pragma unroll
    for (int j4 = 0; j4 < 4; j4++)
        wtail[(half * 4 + j4) * 512 + r] = wrow[12 + j4];

    if (tid < D) hsm[tid] = 0.f;
    float c = 0.f;
    const float* g0 = g_G0 + (size_t)layer * (D * G4);
    float* ws = g_W + layer * D * D;
    __syncthreads();

    const ulonglong2* h2 = (const ulonglong2*)(hsm + half * 64);
    const ulonglong2* wt_base = wtail + half * 4 * 512 + r;

    for (int t = 0; t < D; t++) {
        float q0, q1, q2, q3;
        if (tid < D) {
            const float* gp = g0 + t * G4 + tid;
            q0 = __ldg(gp); q1 = __ldg(gp + 128);
            q2 = __ldg(gp + 256); q3 = __ldg(gp + 384);
        }

        unsigned long long acc = 0ull;
#pragma unroll
        for (int j = 0; j < 12; j++) {
            ulonglong2 hh = h2[j];
            acc = fma2(wreg[2 * j],     hh.x, acc);
            acc = fma2(wreg[2 * j + 1], hh.y, acc);
        }
#pragma unroll
        for (int j4 = 0; j4 < 4; j4++) {
            ulonglong2 w = wt_base[j4 * 512];
            ulonglong2 hh = h2[12 + j4];
            acc = fma2(w.x, hh.x, acc);
            acc = fma2(w.y, hh.y, acc);
        }
        partial[tid] = hsum2(acc);
        __syncthreads();

        if (tid < D) {
            float gi = q0 + partial[tid]       + partial[tid + 512];
            float gf = q1 + partial[tid + 128] + partial[tid + 640];
            float gg = q2 + partial[tid + 256] + partial[tid + 768];
            float go = q3 + partial[tid + 384] + partial[tid + 896];
            float iv = sig_fast(gi), fv = sig_fast(gf);
            float gv = tanh_fast(gg), ov = sig_fast(go);
            c = fmaf(fv, c, iv * gv);
            float h = ov * tanh_fast(c);
            hsm[tid] = h;
            ws[t * D + tid] = h;
        }
        __syncthreads();
    }
}

// ---------------- GAT ----------------

// ft = nf @ W ; s_src = nf @ a_src ; s_dst = nf @ a_dst. Warp-per-row, W in smem.
__global__ void __launch_bounds__(256) k_gat_gemm(
    const float* __restrict__ nf_ext, int layer, const float* __restrict__ a_w)
{
    extern __shared__ float sh[];
    float* Wsm  = sh;              // 128*128
    float* av   = sh + D * D;      // a_src[128], a_dst[128]
    float* xbuf = av + 2 * D;      // 8 warps * 128
    int tid = threadIdx.x;
    const float* Wg = g_W + layer * D * D;
    for (int i = tid; i < D * D; i += 256) Wsm[i] = Wg[i];
    const float* aw = a_w + layer * (2 * D + DE);
    if (tid < D) { av[tid] = aw[tid]; av[D + tid] = aw[D + DE + tid]; }
    __syncthreads();

    const float* nf = layer ? g_feat : nf_ext;
    int warp = tid >> 5, lane = tid & 31;
    int row = blockIdx.x * 8 + warp;
    if (row >= NN) return;

    float* xb = xbuf + warp * D;
    float4 x = ((const float4*)(nf + (size_t)row * D))[lane];
    ((float4*)xb)[lane] = x;
    __syncwarp();

    float ss = x.x * av[lane * 4] + x.y * av[lane * 4 + 1]
             + x.z * av[lane * 4 + 2] + x.w * av[lane * 4 + 3];
    float sd = x.x * av[D + lane * 4] + x.y * av[D + lane * 4 + 1]
             + x.z * av[D + lane * 4 + 2] + x.w * av[D + lane * 4 + 3];

    float4 acc = make_float4(0.f, 0.f, 0.f, 0.f);
    const float4* W4  = (const float4*)Wsm;
    const float4* xb4 = (const float4*)xb;
#pragma unroll 8
    for (int k4 = 0; k4 < 32; k4++) {
        float4 xk = xb4[k4];
        float4 w;
        w = W4[(k4 * 4 + 0) * 32 + lane];
        acc.x = fmaf(xk.x, w.x, acc.x); acc.y = fmaf(xk.x, w.y, acc.y);
        acc.z = fmaf(xk.x, w.z, acc.z); acc.w = fmaf(xk.x, w.w, acc.w);
        w = W4[(k4 * 4 + 1) * 32 + lane];
        acc.x = fmaf(xk.y, w.x, acc.x); acc.y = fmaf(xk.y, w.y, acc.y);
        acc.z = fmaf(xk.y, w.z, acc.z); acc.w = fmaf(xk.y, w.w, acc.w);
        w = W4[(k4 * 4 + 2) * 32 + lane];
        acc.x = fmaf(xk.z, w.x, acc.x); acc.y = fmaf(xk.z, w.y, acc.y);
        acc.z = fmaf(xk.z, w.z, acc.z); acc.w = fmaf(xk.z, w.w, acc.w);
        w = W4[(k4 * 4 + 3) * 32 + lane];
        acc.x = fmaf(xk.w, w.x, acc.x); acc.y = fmaf(xk.w, w.y, acc.y);
        acc.z = fmaf(xk.w, w.z, acc.z); acc.w = fmaf(xk.w, w.w, acc.w);
    }
    ((float4*)(g_ft + (size_t)row * D))[lane] = acc;

#pragma unroll
    for (int o = 16; o; o >>= 1) {
        ss += __shfl_down_sync(0xffffffffu, ss, o);
        sd += __shfl_down_sync(0xffffffffu, sd, o);
    }
    if (lane == 0) { g_ssrc[row] = ss; g_sdst[row] = sd; }
}

// edge scores in original edge order (coalesced ef reads, no atomics)
__global__ void __launch_bounds__(256) k_edge_score(
    const int* __restrict__ src, const int* __restrict__ dst,
    const float* __restrict__ ef, const float* __restrict__ a_w,
    int layer, int n_edges)
{
    int e = blockIdx.x * 256 + threadIdx.x;
    if (e >= n_edges) return;
    const float* ae = a_w + layer * (2 * D + DE) + D;
    int s = src[e], d = dst[e];
    const float4* ep = (const float4*)(ef + (size_t)e * DE);
    float sc = g_ssrc[s] + g_sdst[d];
#pragma unroll
    for (int i = 0; i < 4; i++) {
        float4 v = ep[i];
        sc += v.x * __ldg(ae + i * 4) + v.y * __ldg(ae + i * 4 + 1)
            + v.z * __ldg(ae + i * 4 + 2) + v.w * __ldg(ae + i * 4 + 3);
    }
    g_sc[e] = sc;
}

// fused per-node softmax + aggregation: warp per dst node, zero atomics.
// dest resolved IN DEVICE CODE (round-4 bug: host-side &g_feat is garbage).
__global__ void __launch_bounds__(256) k_node_fused(float* __restrict__ dest_ext, int to_internal)
{
    int n = (blockIdx.x * 256 + threadIdx.x) >> 5;
    int lane = threadIdx.x & 31;
    if (n >= NN) return;
    float* dest = to_internal ? g_feat : dest_ext;
    int off = g_cnt[n], end = g_cnt[n + 1];

    float m = -1e30f;
    for (int j = off + lane; j < end; j += 32)
        m = fmaxf(m, g_sc[g_eid[j]]);
#pragma unroll
    for (int o = 16; o; o >>= 1)
        m = fmaxf(m, __shfl_xor_sync(0xffffffffu, m, o));

    float den = 0.f;
    for (int j = off + lane; j < end; j += 32)
        den += __expf(g_sc[g_eid[j]] - m);
#pragma unroll
    for (int o = 16; o; o >>= 1)
        den += __shfl_xor_sync(0xffffffffu, den, o);
    float inv_den = den > 0.f ? __fdividef(1.f, den) : 0.f;

    float4 acc = make_float4(0.f, 0.f, 0.f, 0.f);
    for (int jb = off; jb < end; jb += 32) {
        int j = jb + lane;
        float al = 0.f; int sv = 0;
        if (j < end) {
            sv = g_ssorted[j];
            al = __expf(g_sc[g_eid[j]] - m) * inv_den;
        }
        int cnt = min(32, end - jb);
        for (int k = 0; k < cnt; k++) {
            float a   = __shfl_sync(0xffffffffu, al, k);
            int  srow = __shfl_sync(0xffffffffu, sv, k);
            float4 v = ((const float4*)(g_ft + (size_t)srow * D))[lane];
            acc.x = fmaf(a, v.x, acc.x); acc.y = fmaf(a, v.y, acc.y);
            acc.z = fmaf(a, v.z, acc.z); acc.w = fmaf(a, v.w, acc.w);
        }
    }
    // leaky_relu (slope 0.01)
    acc.x = acc.x >= 0.f ? acc.x : 0.01f * acc.x;
    acc.y = acc.y >= 0.f ? acc.y : 0.01f * acc.y;
    acc.z = acc.z >= 0.f ? acc.z : 0.01f * acc.z;
    acc.w = acc.w >= 0.f ? acc.w : 0.01f * acc.w;
    ((float4*)(dest + (size_t)n * D))[lane] = acc;
}

// ---------------- launch ----------------
extern "C" void kernel_launch(void* const* d_in, const int* in_sizes, int n_in,
                              void* d_out, int out_size)
{
    const int*   src     = (const int*)  d_in[0];
    const int*   dst     = (const int*)  d_in[1];
    const float* n_feats = (const float*)d_in[2];
    const float* e_feats = (const float*)d_in[3];
    const float* W0      = (const float*)d_in[4];
    const float* Wih     = (const float*)d_in[5];
    const float* Whh     = (const float*)d_in[6];
    const float* bih     = (const float*)d_in[7];
    const float* bhh     = (const float*)d_in[8];
    const float* a_w     = (const float*)d_in[9];

    int n_edges = in_sizes[0] / 3;        // 800000
    int n_nodes = in_sizes[2] / (3 * D);  // 50000

    int smem_rec  = (8 * 512 * 4 + 128 + 1024) * (int)sizeof(float);   // ~69.1KB
    int smem_gemm = (D * D + 2 * D + 8 * D) * (int)sizeof(float);      // ~70.5KB
    cudaFuncSetAttribute(k_lstm_rec, cudaFuncAttributeMaxDynamicSharedMemorySize, smem_rec);
    cudaFuncSetAttribute(k_gat_gemm, cudaFuncAttributeMaxDynamicSharedMemorySize, smem_gemm);

    // only timestep j=2 matters for the output (feats never mix across j)
    const int*   src2 = src + 2 * n_edges;
    const int*   dst2 = dst + 2 * n_edges;
    const float* nf2  = n_feats + (size_t)2 * n_nodes * D;
    const float* ef2  = e_feats + (size_t)2 * n_edges * DE;

    // --- build dst-sorted edge structure once (shared by both layers) ---
    k_zero_cnt<<<(NN + 256) / 256, 256>>>();
    k_hist<<<(n_edges + 255) / 256, 256>>>(dst2);
    k_scan<<<1, 1024>>>();
    k_scatter<<<(n_edges + 255) / 256, 256>>>(src2, dst2);

    // --- LSTM chains for both layers (grid.y / grid.x = 2) ---
    k_transpose_wih<<<(2 * G4 * D + 255) / 256, 256>>>(Wih);
    for (int call = 0; call < 3; call++) {
        k_lstm_g0<<<dim3(D, 2), 512>>>(W0, call > 0, bih, bhh);
        k_lstm_rec<<<2, 1024, smem_rec>>>(Whh);
    }

    // --- GAT layers (atomic-free) ---
    for (int layer = 0; layer < 2; layer++) {
        k_gat_gemm<<<(n_nodes + 7) / 8, 256, smem_gemm>>>(nf2, layer, a_w);
        k_edge_score<<<(n_edges + 255) / 256, 256>>>(src2, dst2, ef2, a_w, layer, n_edges);
        k_node_fused<<<(n_nodes * 32 + 255) / 256, 256>>>((float*)d_out, layer == 0 ? 1 : 0);
    }
}

// round 7
// speedup vs baseline: 1.3490x; 1.2135x over previous
#include <cuda_runtime.h>
#include <math.h>
#include <stdint.h>

#define NN 50000
#define NE 800000
#define D  128
#define DE 16
#define G4 512   // 4*D gates

// ---------------- scratch (static device globals; no allocation) ----------------
__device__ __align__(16) float g_W[2 * D * D];        // evolving LSTM state (hs) per layer
__device__ __align__(16) float g_G0[2 * D * G4];      // precomputed Wih@x + b per layer
__device__ __align__(16) float g_WihT[2 * D * G4];    // transposed Wih for coalesced G0 GEMM
__device__ __align__(16) float g_ft[(size_t)NN * D];  // nf @ W
__device__ __align__(16) float g_feat[(size_t)NN * D];// layer-0 GAT output (post leaky)
__device__ float g_sc2[NE];       // edge score in dst-sorted order (then exp in place)
__device__ float g_ssrc[NN];
__device__ float g_sdst[NN];
// ---- dst-sorted edge structure (built once; graph identical across layers) ----
__device__ int g_cnt[NN + 1];     // counts -> exclusive offsets (in place)
__device__ int g_cur[NN];         // scatter cursors
__device__ int g_epos[NE];        // original edge id -> sorted position
__device__ int g_ssorted[NE];     // sorted position -> src node

// packed f32x2 FMA (sm_103a FFMA2) — PTX-only, ptxas won't auto-fuse
__device__ __forceinline__ unsigned long long fma2(
    unsigned long long a, unsigned long long b, unsigned long long c)
{
    unsigned long long d;
    asm("fma.rn.f32x2 %0, %1, %2, %3;" : "=l"(d) : "l"(a), "l"(b), "l"(c));
    return d;
}
__device__ __forceinline__ unsigned long long dup2(float x) {
    unsigned long long r;
    asm("mov.b64 %0, {%1,%1};" : "=l"(r) : "r"(__float_as_uint(x)));
    return r;
}
__device__ __forceinline__ float hsum2(unsigned long long a) {
    return __uint_as_float((unsigned)a) + __uint_as_float((unsigned)(a >> 32));
}
__device__ __forceinline__ float lo2(unsigned long long a) { return __uint_as_float((unsigned)a); }
__device__ __forceinline__ float hi2(unsigned long long a) { return __uint_as_float((unsigned)(a >> 32)); }
__device__ __forceinline__ float tanh_fast(float x) {
    float r; asm("tanh.approx.f32 %0, %1;" : "=f"(r) : "f"(x)); return r;
}
__device__ __forceinline__ float sig_fast(float x) {
    return __fdividef(1.f, 1.f + __expf(-x));
}

// ---------------- edge sort (once) ----------------

__global__ void k_zero_cnt() {
    int idx = blockIdx.x * 256 + threadIdx.x;
    if (idx <= NN) g_cnt[idx] = 0;
}

__global__ void k_hist(const int* __restrict__ dst) {
    int e = blockIdx.x * 256 + threadIdx.x;
    if (e < NE) atomicAdd(&g_cnt[dst[e]], 1);
}

// single-CTA exclusive scan over 50k counts; writes offsets into g_cnt and g_cur
__global__ void __launch_bounds__(1024) k_scan() {
    const int CH = 49;                     // 1024*49 = 50176 >= NN
    int tid = threadIdx.x;
    int lane = tid & 31, wid = tid >> 5;
    int base = tid * CH;
    int s = 0;
    for (int i = 0; i < CH; i++) {
        int j = base + i;
        if (j < NN) s += g_cnt[j];
    }
    __shared__ int wsum[32];
    int v = s;
#pragma unroll
    for (int o = 1; o < 32; o <<= 1) {
        int t = __shfl_up_sync(0xffffffffu, v, o);
        if (lane >= o) v += t;
    }
    if (lane == 31) wsum[wid] = v;
    __syncthreads();
    if (wid == 0) {
        int w = wsum[lane];
#pragma unroll
        for (int o = 1; o < 32; o <<= 1) {
            int t = __shfl_up_sync(0xffffffffu, w, o);
            if (lane >= o) w += t;
        }
        wsum[lane] = w;
    }
    __syncthreads();
    int run = v - s + (wid ? wsum[wid - 1] : 0);   // exclusive prefix
    for (int i = 0; i < CH; i++) {
        int j = base + i;
        if (j < NN) {
            int c = g_cnt[j];
            g_cnt[j] = run;
            g_cur[j] = run;
            run += c;
        }
    }
    if (tid == 1023) g_cnt[NN] = NE;
}

__global__ void k_scatter(const int* __restrict__ src, const int* __restrict__ dst) {
    int e = blockIdx.x * 256 + threadIdx.x;
    if (e >= NE) return;
    int d = dst[e];
    int pos = atomicAdd(&g_cur[d], 1);
    g_epos[e] = pos;
    g_ssorted[pos] = src[e];
}

// ---------------- LSTM ----------------

// transpose Wih (L,512,128) -> WihT (L,128,512) for coalesced reads in G0
__global__ void k_transpose_wih(const float* __restrict__ Wih) {
    int idx = blockIdx.x * 256 + threadIdx.x;
    if (idx >= 2 * G4 * D) return;
    int layer = idx / (G4 * D);
    int rem   = idx - layer * (G4 * D);
    int g = rem / D, k = rem % D;
    g_WihT[(size_t)layer * (D * G4) + k * G4 + g] = Wih[idx];
}

// G0[t][g] = b[g] + sum_k X[t][k] * Wih[g][k]
__global__ void __launch_bounds__(512) k_lstm_g0(
    const float* __restrict__ Xext, int use_state,
    const float* __restrict__ bih, const float* __restrict__ bhh)
{
    int t = blockIdx.x, layer = blockIdx.y;
    int g = threadIdx.x;
    __shared__ float xs[D];
    const float* X = use_state ? (g_W + layer * D * D) : (Xext + layer * D * D);
    if (g < D) xs[g] = X[t * D + g];
    __syncthreads();
    const float* wt = g_WihT + (size_t)layer * (D * G4) + g;
    float a0 = bih[layer * G4 + g] + bhh[layer * G4 + g];
    float a1 = 0.f, a2 = 0.f, a3 = 0.f;
#pragma unroll
    for (int k = 0; k < D; k += 4) {
        a0 = fmaf(wt[(k + 0) * G4], xs[k + 0], a0);
        a1 = fmaf(wt[(k + 1) * G4], xs[k + 1], a1);
        a2 = fmaf(wt[(k + 2) * G4], xs[k + 2], a2);
        a3 = fmaf(wt[(k + 3) * G4], xs[k + 3], a3);
    }
    g_G0[(size_t)(layer * D + t) * G4 + g] = (a0 + a1) + (a2 + a3);
}

// 128-step recurrence, one CTA of 1024 threads per layer (grid=2).
__global__ void __launch_bounds__(1024, 1) k_lstm_rec(const float* __restrict__ Whh)
{
    int layer = blockIdx.x;
    extern __shared__ float sh[];
    ulonglong2* wtail = (ulonglong2*)sh;                 // 8*512 u128 = 64KB
    float* hsm     = sh + 8 * 512 * 4;                   // 128 floats
    float* partial = hsm + 128;                          // 1024 floats

    int tid  = threadIdx.x;
    int half = tid >> 9;
    int r    = tid & 511;

    const ulonglong2* wrow =
        (const ulonglong2*)(Whh + ((size_t)(layer * G4 + r)) * D + half * 64);
    unsigned long long wreg[24];
#pragma unroll
    for (int j = 0; j < 12; j++) {
        ulonglong2 v = wrow[j];
        wreg[2 * j] = v.x; wreg[2 * j + 1] = v.y;
    }
#pragma unroll
    for (int j4 = 0; j4 < 4; j4++)
        wtail[(half * 4 + j4) * 512 + r] = wrow[12 + j4];

    if (tid < D) hsm[tid] = 0.f;
    float c = 0.f;
    const float* g0 = g_G0 + (size_t)layer * (D * G4);
    float* ws = g_W + layer * D * D;
    __syncthreads();

    const ulonglong2* h2 = (const ulonglong2*)(hsm + half * 64);
    const ulonglong2* wt_base = wtail + half * 4 * 512 + r;

    for (int t = 0; t < D; t++) {
        float q0, q1, q2, q3;
        if (tid < D) {
            const float* gp = g0 + t * G4 + tid;
            q0 = __ldg(gp); q1 = __ldg(gp + 128);
            q2 = __ldg(gp + 256); q3 = __ldg(gp + 384);
        }

        unsigned long long acc = 0ull;
#pragma unroll
        for (int j = 0; j < 12; j++) {
            ulonglong2 hh = h2[j];
            acc = fma2(wreg[2 * j],     hh.x, acc);
            acc = fma2(wreg[2 * j + 1], hh.y, acc);
        }
#pragma unroll
        for (int j4 = 0; j4 < 4; j4++) {
            ulonglong2 w = wt_base[j4 * 512];
            ulonglong2 hh = h2[12 + j4];
            acc = fma2(w.x, hh.x, acc);
            acc = fma2(w.y, hh.y, acc);
        }
        partial[tid] = hsum2(acc);
        __syncthreads();

        if (tid < D) {
            float gi = q0 + partial[tid]       + partial[tid + 512];
            float gf = q1 + partial[tid + 128] + partial[tid + 640];
            float gg = q2 + partial[tid + 256] + partial[tid + 768];
            float go = q3 + partial[tid + 384] + partial[tid + 896];
            float iv = sig_fast(gi), fv = sig_fast(gf);
            float gv = tanh_fast(gg), ov = sig_fast(go);
            c = fmaf(fv, c, iv * gv);
            float h = ov * tanh_fast(c);
            hsm[tid] = h;
            ws[t * D + tid] = h;
        }
        __syncthreads();
    }
}

// ---------------- GAT ----------------

// Register-tiled GEMM: CTA = 64 rows x 128 cols, thread = 8 rows x 4 cols.
// X loads are warp-broadcasts; W loads amortize over 8 rows; packed fma2.
// Also emits s_src/s_dst per row. Predicted ~30us/layer (FMA floor) vs ~125us before.
__global__ void __launch_bounds__(256, 2) k_gat_gemm(
    const float* __restrict__ nf_ext, int layer, const float* __restrict__ a_w)
{
    extern __shared__ float sh[];
    float* Wsm = sh;               // 16384 floats (64KB)
    float* Xs  = sh + D * D;       // 64*128 floats (32KB)
    float* av  = Xs + 64 * D;      // a_src[128], a_dst[128]
    int tid = threadIdx.x;

    const float4* Wg4 = (const float4*)(g_W + layer * D * D);
    float4* Wsm4 = (float4*)Wsm;
    for (int i = tid; i < D * D / 4; i += 256) Wsm4[i] = Wg4[i];

    const float* aw = a_w + layer * (2 * D + DE);
    if (tid < D) { av[tid] = aw[tid]; av[D + tid] = aw[D + DE + tid]; }

    const float* nf = layer ? g_feat : nf_ext;
    int row0 = blockIdx.x * 64;
    float4* Xs4 = (float4*)Xs;
    for (int i = tid; i < 64 * 32; i += 256) {
        int r = i >> 5, cc = i & 31;
        int gr = row0 + r;
        float4 v = make_float4(0.f, 0.f, 0.f, 0.f);
        if (gr < NN) v = ((const float4*)(nf + (size_t)gr * D))[cc];
        Xs4[i] = v;
    }
    __syncthreads();

    int lane = tid & 31, wid = tid >> 5;

    // per-row attention scores (warp wid handles local rows wid*8..+7)
    const float4* as4 = (const float4*)av;
    const float4* ad4 = (const float4*)(av + D);
#pragma unroll
    for (int i = 0; i < 8; i++) {
        int lr = wid * 8 + i;
        float4 x = Xs4[lr * 32 + lane];
        float4 a = as4[lane], b = ad4[lane];
        float ss = x.x * a.x + x.y * a.y + x.z * a.z + x.w * a.w;
        float sd = x.x * b.x + x.y * b.y + x.z * b.z + x.w * b.w;
#pragma unroll
        for (int o = 16; o; o >>= 1) {
            ss += __shfl_xor_sync(0xffffffffu, ss, o);
            sd += __shfl_xor_sync(0xffffffffu, sd, o);
        }
        int gr = row0 + lr;
        if (lane == 0 && gr < NN) { g_ssrc[gr] = ss; g_sdst[gr] = sd; }
    }

    // main GEMM
    const ulonglong2* W2 = (const ulonglong2*)Wsm;   // row k: 32 ulonglong2
    unsigned long long acc[8][2];
#pragma unroll
    for (int i = 0; i < 8; i++) { acc[i][0] = 0ull; acc[i][1] = 0ull; }

#pragma unroll 8
    for (int k4 = 0; k4 < 32; k4++) {
        ulonglong2 w0 = W2[(k4 * 4 + 0) * 32 + lane];
        ulonglong2 w1 = W2[(k4 * 4 + 1) * 32 + lane];
        ulonglong2 w2 = W2[(k4 * 4 + 2) * 32 + lane];
        ulonglong2 w3 = W2[(k4 * 4 + 3) * 32 + lane];
#pragma unroll
        for (int i = 0; i < 8; i++) {
            float4 xv = Xs4[(wid * 8 + i) * 32 + k4];   // broadcast (same addr per warp)
            unsigned long long xx;
            xx = dup2(xv.x);
            acc[i][0] = fma2(w0.x, xx, acc[i][0]); acc[i][1] = fma2(w0.y, xx, acc[i][1]);
            xx = dup2(xv.y);
            acc[i][0] = fma2(w1.x, xx, acc[i][0]); acc[i][1] = fma2(w1.y, xx, acc[i][1]);
            xx = dup2(xv.z);
            acc[i][0] = fma2(w2.x, xx, acc[i][0]); acc[i][1] = fma2(w2.y, xx, acc[i][1]);
            xx = dup2(xv.w);
            acc[i][0] = fma2(w3.x, xx, acc[i][0]); acc[i][1] = fma2(w3.y, xx, acc[i][1]);
        }
    }

#pragma unroll
    for (int i = 0; i < 8; i++) {
        int gr = row0 + wid * 8 + i;
        if (gr < NN) {
            float4 o;
            o.x = lo2(acc[i][0]); o.y = hi2(acc[i][0]);
            o.z = lo2(acc[i][1]); o.w = hi2(acc[i][1]);
            ((float4*)(g_ft + (size_t)gr * D))[lane] = o;
        }
    }
}

// edge scores, written directly into dst-sorted order via g_epos
__global__ void __launch_bounds__(256) k_edge_score(
    const int* __restrict__ src, const int* __restrict__ dst,
    const float* __restrict__ ef, const float* __restrict__ a_w,
    int layer, int n_edges)
{
    int e = blockIdx.x * 256 + threadIdx.x;
    if (e >= n_edges) return;
    const float* ae = a_w + layer * (2 * D + DE) + D;
    int s = src[e], d = dst[e];
    const float4* ep = (const float4*)(ef + (size_t)e * DE);
    float sc = g_ssrc[s] + g_sdst[d];
#pragma unroll
    for (int i = 0; i < 4; i++) {
        float4 v = ep[i];
        sc += v.x * __ldg(ae + i * 4) + v.y * __ldg(ae + i * 4 + 1)
            + v.z * __ldg(ae + i * 4 + 2) + v.w * __ldg(ae + i * 4 + 3);
    }
    g_sc2[g_epos[e]] = sc;
}

// fused per-node softmax + aggregation: warp per dst node, all edge reads coalesced.
// dest resolved IN DEVICE CODE (host-side &g_feat is garbage).
__global__ void __launch_bounds__(256) k_node_fused(float* __restrict__ dest_ext, int to_internal)
{
    int n = (blockIdx.x * 256 + threadIdx.x) >> 5;
    int lane = threadIdx.x & 31;
    if (n >= NN) return;
    float* dest = to_internal ? g_feat : dest_ext;
    int off = g_cnt[n], end = g_cnt[n + 1];

    float m = -1e30f;
    for (int j = off + lane; j < end; j += 32)
        m = fmaxf(m, g_sc2[j]);
#pragma unroll
    for (int o = 16; o; o >>= 1)
        m = fmaxf(m, __shfl_xor_sync(0xffffffffu, m, o));

    float den = 0.f;
    for (int j = off + lane; j < end; j += 32) {
        float ex = __expf(g_sc2[j] - m);
        den += ex;
        g_sc2[j] = ex;   // in-place: same thread re-reads the same index below
    }
#pragma unroll
    for (int o = 16; o; o >>= 1)
        den += __shfl_xor_sync(0xffffffffu, den, o);
    float inv_den = den > 0.f ? __fdividef(1.f, den) : 0.f;

    float4 acc = make_float4(0.f, 0.f, 0.f, 0.f);
    for (int jb = off; jb < end; jb += 32) {
        int j = jb + lane;
        float al = 0.f; int sv = 0;
        if (j < end) {
            sv = g_ssorted[j];
            al = g_sc2[j] * inv_den;
        }
        int cnt = min(32, end - jb);
        for (int k = 0; k < cnt; k++) {
            float a   = __shfl_sync(0xffffffffu, al, k);
            int  srow = __shfl_sync(0xffffffffu, sv, k);
            float4 v = ((const float4*)(g_ft + (size_t)srow * D))[lane];
            acc.x = fmaf(a, v.x, acc.x); acc.y = fmaf(a, v.y, acc.y);
            acc.z = fmaf(a, v.z, acc.z); acc.w = fmaf(a, v.w, acc.w);
        }
    }
    // leaky_relu (slope 0.01)
    acc.x = acc.x >= 0.f ? acc.x : 0.01f * acc.x;
    acc.y = acc.y >= 0.f ? acc.y : 0.01f * acc.y;
    acc.z = acc.z >= 0.f ? acc.z : 0.01f * acc.z;
    acc.w = acc.w >= 0.f ? acc.w : 0.01f * acc.w;
    ((float4*)(dest + (size_t)n * D))[lane] = acc;
}

// ---------------- launch ----------------
extern "C" void kernel_launch(void* const* d_in, const int* in_sizes, int n_in,
                              void* d_out, int out_size)
{
    const int*   src     = (const int*)  d_in[0];
    const int*   dst     = (const int*)  d_in[1];
    const float* n_feats = (const float*)d_in[2];
    const float* e_feats = (const float*)d_in[3];
    const float* W0      = (const float*)d_in[4];
    const float* Wih     = (const float*)d_in[5];
    const float* Whh     = (const float*)d_in[6];
    const float* bih     = (const float*)d_in[7];
    const float* bhh     = (const float*)d_in[8];
    const float* a_w     = (const float*)d_in[9];

    int n_edges = in_sizes[0] / 3;        // 800000
    int n_nodes = in_sizes[2] / (3 * D);  // 50000

    int smem_rec  = (8 * 512 * 4 + 128 + 1024) * (int)sizeof(float);   // ~69.1KB
    int smem_gemm = (D * D + 64 * D + 2 * D) * (int)sizeof(float);     // ~97KB
    cudaFuncSetAttribute(k_lstm_rec, cudaFuncAttributeMaxDynamicSharedMemorySize, smem_rec);
    cudaFuncSetAttribute(k_gat_gemm, cudaFuncAttributeMaxDynamicSharedMemorySize, smem_gemm);

    // only timestep j=2 matters for the output (feats never mix across j)
    const int*   src2 = src + 2 * n_edges;
    const int*   dst2 = dst + 2 * n_edges;
    const float* nf2  = n_feats + (size_t)2 * n_nodes * D;
    const float* ef2  = e_feats + (size_t)2 * n_edges * DE;

    // --- build dst-sorted edge structure once (shared by both layers) ---
    k_zero_cnt<<<(NN + 256) / 256, 256>>>();
    k_hist<<<(n_edges + 255) / 256, 256>>>(dst2);
    k_scan<<<1, 1024>>>();
    k_scatter<<<(n_edges + 255) / 256, 256>>>(src2, dst2);

    // --- LSTM chains for both layers (grid.y / grid.x = 2) ---
    k_transpose_wih<<<(2 * G4 * D + 255) / 256, 256>>>(Wih);
    for (int call = 0; call < 3; call++) {
        k_lstm_g0<<<dim3(D, 2), 512>>>(W0, call > 0, bih, bhh);
        k_lstm_rec<<<2, 1024, smem_rec>>>(Whh);
    }

    // --- GAT layers (atomic-free, coalesced edge passes) ---
    for (int layer = 0; layer < 2; layer++) {
        k_gat_gemm<<<(n_nodes + 63) / 64, 256, smem_gemm>>>(nf2, layer, a_w);
        k_edge_score<<<(n_edges + 255) / 256, 256>>>(src2, dst2, ef2, a_w, layer, n_edges);
        k_node_fused<<<(n_nodes * 32 + 255) / 256, 256>>>((float*)d_out, layer == 0 ? 1 : 0);
    }
}

// round 8
// speedup vs baseline: 1.4819x; 1.0985x over previous
#include <cuda_runtime.h>
#include <math.h>
#include <stdint.h>

#define NN 50000
#define NE 800000
#define D  128
#define DE 16
#define G4 512   // 4*D gates

// ---------------- scratch (static device globals; no allocation) ----------------
__device__ __align__(16) float g_W[2 * D * D];        // evolving LSTM state (hs) per layer
__device__ __align__(16) float g_G0[2 * D * G4];      // precomputed Wih@x + b per layer
__device__ __align__(16) float g_WihT[2 * D * G4];    // transposed Wih for coalesced G0 GEMM
__device__ __align__(16) float g_ft[(size_t)NN * D];  // nf @ W
__device__ __align__(16) float g_feat[(size_t)NN * D];// layer-0 GAT output (post leaky)
__device__ float g_sc2[NE];       // edge score in dst-sorted order
__device__ float g_edot[2 * NE];  // ef @ a_edge per layer, dst-sorted order
__device__ float g_ssrc[NN];
__device__ float g_sdst[NN];
// ---- dst-sorted edge structure (built once; graph identical across layers) ----
__device__ int g_cnt[NN + 1];     // counts -> exclusive offsets (in place)
__device__ int g_cur[NN];         // scatter cursors
__device__ int g_ssorted[NE];     // sorted position -> src node

// packed f32x2 FMA (sm_103a FFMA2) — PTX-only, ptxas won't auto-fuse
__device__ __forceinline__ unsigned long long fma2(
    unsigned long long a, unsigned long long b, unsigned long long c)
{
    unsigned long long d;
    asm("fma.rn.f32x2 %0, %1, %2, %3;" : "=l"(d) : "l"(a), "l"(b), "l"(c));
    return d;
}
__device__ __forceinline__ unsigned long long dup2(float x) {
    unsigned long long r;
    asm("mov.b64 %0, {%1,%1};" : "=l"(r) : "r"(__float_as_uint(x)));
    return r;
}
__device__ __forceinline__ float hsum2(unsigned long long a) {
    return __uint_as_float((unsigned)a) + __uint_as_float((unsigned)(a >> 32));
}
__device__ __forceinline__ float lo2(unsigned long long a) { return __uint_as_float((unsigned)a); }
__device__ __forceinline__ float hi2(unsigned long long a) { return __uint_as_float((unsigned)(a >> 32)); }
__device__ __forceinline__ float tanh_fast(float x) {
    float r; asm("tanh.approx.f32 %0, %1;" : "=f"(r) : "f"(x)); return r;
}
__device__ __forceinline__ float sig_fast(float x) {
    return __fdividef(1.f, 1.f + __expf(-x));
}

// ---------------- edge sort (once) ----------------

__global__ void k_zero_cnt() {
    int idx = blockIdx.x * 256 + threadIdx.x;
    if (idx <= NN) g_cnt[idx] = 0;
}

__global__ void k_hist(const int* __restrict__ dst) {
    int e = blockIdx.x * 256 + threadIdx.x;
    if (e < NE) atomicAdd(&g_cnt[dst[e]], 1);
}

// single-CTA exclusive scan over 50k counts; writes offsets into g_cnt and g_cur
__global__ void __launch_bounds__(1024) k_scan() {
    const int CH = 49;                     // 1024*49 = 50176 >= NN
    int tid = threadIdx.x;
    int lane = tid & 31, wid = tid >> 5;
    int base = tid * CH;
    int s = 0;
    for (int i = 0; i < CH; i++) {
        int j = base + i;
        if (j < NN) s += g_cnt[j];
    }
    __shared__ int wsum[32];
    int v = s;
#pragma unroll
    for (int o = 1; o < 32; o <<= 1) {
        int t = __shfl_up_sync(0xffffffffu, v, o);
        if (lane >= o) v += t;
    }
    if (lane == 31) wsum[wid] = v;
    __syncthreads();
    if (wid == 0) {
        int w = wsum[lane];
#pragma unroll
        for (int o = 1; o < 32; o <<= 1) {
            int t = __shfl_up_sync(0xffffffffu, w, o);
            if (lane >= o) w += t;
        }
        wsum[lane] = w;
    }
    __syncthreads();
    int run = v - s + (wid ? wsum[wid - 1] : 0);   // exclusive prefix
    for (int i = 0; i < CH; i++) {
        int j = base + i;
        if (j < NN) {
            int c = g_cnt[j];
            g_cnt[j] = run;
            g_cur[j] = run;
            run += c;
        }
    }
    if (tid == 1023) g_cnt[NN] = NE;
}

// scatter + fused edge-feature dot for BOTH layers (ef read once, ever)
__global__ void __launch_bounds__(256) k_scatter(
    const int* __restrict__ src, const int* __restrict__ dst,
    const float* __restrict__ ef, const float* __restrict__ a_w)
{
    int e = blockIdx.x * 256 + threadIdx.x;
    if (e >= NE) return;
    int d = dst[e];
    int pos = atomicAdd(&g_cur[d], 1);
    g_ssorted[pos] = src[e];
    const float4* ep = (const float4*)(ef + (size_t)e * DE);
    const float* ae0 = a_w + D;
    const float* ae1 = a_w + (2 * D + DE) + D;
    float d0 = 0.f, d1 = 0.f;
#pragma unroll
    for (int i = 0; i < 4; i++) {
        float4 v = ep[i];
        d0 += v.x * __ldg(ae0 + i * 4)     + v.y * __ldg(ae0 + i * 4 + 1)
            + v.z * __ldg(ae0 + i * 4 + 2) + v.w * __ldg(ae0 + i * 4 + 3);
        d1 += v.x * __ldg(ae1 + i * 4)     + v.y * __ldg(ae1 + i * 4 + 1)
            + v.z * __ldg(ae1 + i * 4 + 2) + v.w * __ldg(ae1 + i * 4 + 3);
    }
    g_edot[pos]      = d0;
    g_edot[NE + pos] = d1;
}

// ---------------- LSTM ----------------

// transpose Wih (L,512,128) -> WihT (L,128,512) for coalesced reads in G0
__global__ void k_transpose_wih(const float* __restrict__ Wih) {
    int idx = blockIdx.x * 256 + threadIdx.x;
    if (idx >= 2 * G4 * D) return;
    int layer = idx / (G4 * D);
    int rem   = idx - layer * (G4 * D);
    int g = rem / D, k = rem % D;
    g_WihT[(size_t)layer * (D * G4) + k * G4 + g] = Wih[idx];
}

// G0[t][g] = b[g] + sum_k X[t][k] * Wih[g][k]; 4 t-rows per block (WihT reuse 4x)
__global__ void __launch_bounds__(512) k_lstm_g0(
    const float* __restrict__ Xext, int use_state,
    const float* __restrict__ bih, const float* __restrict__ bhh)
{
    int layer = blockIdx.y;
    int t0 = blockIdx.x * 4;
    int g = threadIdx.x;
    __shared__ float xs[4 * D];
    const float* X = use_state ? (g_W + layer * D * D) : (Xext + layer * D * D);
    xs[g] = X[t0 * D + g];   // 512 threads cover rows t0..t0+3 contiguously
    __syncthreads();
    const float* wt = g_WihT + (size_t)layer * (D * G4) + g;
    float b = bih[layer * G4 + g] + bhh[layer * G4 + g];
    float a0 = 0.f, a1 = 0.f, a2 = 0.f, a3 = 0.f;
#pragma unroll 4
    for (int k = 0; k < D; k++) {
        float w = wt[k * G4];
        a0 = fmaf(w, xs[k],         a0);
        a1 = fmaf(w, xs[D + k],     a1);
        a2 = fmaf(w, xs[2 * D + k], a2);
        a3 = fmaf(w, xs[3 * D + k], a3);
    }
    size_t o = (size_t)(layer * D + t0) * G4 + g;
    g_G0[o]          = a0 + b;
    g_G0[o + G4]     = a1 + b;
    g_G0[o + 2 * G4] = a2 + b;
    g_G0[o + 3 * G4] = a3 + b;
}

// 128-step recurrence, one CTA of 1024 threads per layer (grid=2).
// thread = (half = tid>>9, row r = tid&511), k in [half*64, half*64+64):
//   k 0..39 in regs (20 u64 = 40 regs, fits the 64-reg cap WITHOUT spills),
//   k 40..63 in smem (96KB/step crossbar). Activations spread over 512 threads.
__global__ void __launch_bounds__(1024, 1) k_lstm_rec(const float* __restrict__ Whh)
{
    int layer = blockIdx.x;
    extern __shared__ float sh[];
    float4* wsm  = (float4*)sh;              // [6][1024] u128 = 96KB
    float*  hsm  = sh + 6 * 1024 * 4;        // 128 floats
    float*  part = hsm + 128;                // 512 floats (upper-half partials)
    float*  gsm  = part + 512;               // 512 floats (activations)

    int tid  = threadIdx.x;
    int half = tid >> 9;
    int r    = tid & 511;

    const float* wrow = Whh + ((size_t)(layer * G4 + r)) * D + half * 64;
    unsigned long long wreg[20];
#pragma unroll
    for (int j = 0; j < 20; j++)
        wreg[j] = *(const unsigned long long*)(wrow + 2 * j);
#pragma unroll
    for (int j = 0; j < 6; j++)
        wsm[j * 1024 + tid] = *(const float4*)(wrow + 40 + 4 * j);

    if (tid < D) hsm[tid] = 0.f;
    float c = 0.f;
    const float* g0 = g_G0 + (size_t)layer * (D * G4);
    float* ws = g_W + layer * D * D;
    __syncthreads();

    const ulonglong2* h2 = (const ulonglong2*)(hsm + half * 64);
    const ulonglong2* wt = (const ulonglong2*)wsm + tid;

    for (int t = 0; t < D; t++) {
        float q = 0.f;
        if (tid < 512) q = __ldg(g0 + t * G4 + tid);

        unsigned long long a0 = 0ull, a1 = 0ull;
#pragma unroll
        for (int j = 0; j < 10; j++) {
            ulonglong2 hh = h2[j];
            a0 = fma2(wreg[2 * j],     hh.x, a0);
            a1 = fma2(wreg[2 * j + 1], hh.y, a1);
        }
#pragma unroll
        for (int j = 0; j < 6; j++) {
            ulonglong2 w  = wt[j * 1024];
            ulonglong2 hh = h2[10 + j];
            a0 = fma2(w.x, hh.x, a0);
            a1 = fma2(w.y, hh.y, a1);
        }
        float own = hsum2(a0) + hsum2(a1);
        if (tid >= 512) part[r] = own;
        __syncthreads();

        if (tid < 512) {
            float gate = q + own + part[tid];
            float act = (tid >= 256 && tid < 384) ? tanh_fast(gate) : sig_fast(gate);
            gsm[tid] = act;
        }
        __syncthreads();

        if (tid < D) {
            float iv = gsm[tid], fv = gsm[tid + 128];
            float gv = gsm[tid + 256], ov = gsm[tid + 384];
            c = fmaf(fv, c, iv * gv);
            float h = ov * tanh_fast(c);
            hsm[tid] = h;
            ws[t * D + tid] = h;
        }
        __syncthreads();
    }
}

// ---------------- GAT ----------------

// Register-tiled GEMM: CTA = 64 rows x 128 cols, thread = 8 rows x 4 cols.
__global__ void __launch_bounds__(256, 2) k_gat_gemm(
    const float* __restrict__ nf_ext, int layer, const float* __restrict__ a_w)
{
    extern __shared__ float sh[];
    float* Wsm = sh;               // 16384 floats (64KB)
    float* Xs  = sh + D * D;       // 64*128 floats (32KB)
    float* av  = Xs + 64 * D;      // a_src[128], a_dst[128]
    int tid = threadIdx.x;

    const float4* Wg4 = (const float4*)(g_W + layer * D * D);
    float4* Wsm4 = (float4*)Wsm;
    for (int i = tid; i < D * D / 4; i += 256) Wsm4[i] = Wg4[i];

    const float* aw = a_w + layer * (2 * D + DE);
    if (tid < D) { av[tid] = aw[tid]; av[D + tid] = aw[D + DE + tid]; }

    const float* nf = layer ? g_feat : nf_ext;
    int row0 = blockIdx.x * 64;
    float4* Xs4 = (float4*)Xs;
    for (int i = tid; i < 64 * 32; i += 256) {
        int r = i >> 5, cc = i & 31;
        int gr = row0 + r;
        float4 v = make_float4(0.f, 0.f, 0.f, 0.f);
        if (gr < NN) v = ((const float4*)(nf + (size_t)gr * D))[cc];
        Xs4[i] = v;
    }
    __syncthreads();

    int lane = tid & 31, wid = tid >> 5;

    const float4* as4 = (const float4*)av;
    const float4* ad4 = (const float4*)(av + D);
#pragma unroll
    for (int i = 0; i < 8; i++) {
        int lr = wid * 8 + i;
        float4 x = Xs4[lr * 32 + lane];
        float4 a = as4[lane], b = ad4[lane];
        float ss = x.x * a.x + x.y * a.y + x.z * a.z + x.w * a.w;
        float sd = x.x * b.x + x.y * b.y + x.z * b.z + x.w * b.w;
#pragma unroll
        for (int o = 16; o; o >>= 1) {
            ss += __shfl_xor_sync(0xffffffffu, ss, o);
            sd += __shfl_xor_sync(0xffffffffu, sd, o);
        }
        int gr = row0 + lr;
        if (lane == 0 && gr < NN) { g_ssrc[gr] = ss; g_sdst[gr] = sd; }
    }

    const ulonglong2* W2 = (const ulonglong2*)Wsm;
    unsigned long long acc[8][2];
#pragma unroll
    for (int i = 0; i < 8; i++) { acc[i][0] = 0ull; acc[i][1] = 0ull; }

#pragma unroll 8
    for (int k4 = 0; k4 < 32; k4++) {
        ulonglong2 w0 = W2[(k4 * 4 + 0) * 32 + lane];
        ulonglong2 w1 = W2[(k4 * 4 + 1) * 32 + lane];
        ulonglong2 w2 = W2[(k4 * 4 + 2) * 32 + lane];
        ulonglong2 w3 = W2[(k4 * 4 + 3) * 32 + lane];
#pragma unroll
        for (int i = 0; i < 8; i++) {
            float4 xv = Xs4[(wid * 8 + i) * 32 + k4];
            unsigned long long xx;
            xx = dup2(xv.x);
            acc[i][0] = fma2(w0.x, xx, acc[i][0]); acc[i][1] = fma2(w0.y, xx, acc[i][1]);
            xx = dup2(xv.y);
            acc[i][0] = fma2(w1.x, xx, acc[i][0]); acc[i][1] = fma2(w1.y, xx, acc[i][1]);
            xx = dup2(xv.z);
            acc[i][0] = fma2(w2.x, xx, acc[i][0]); acc[i][1] = fma2(w2.y, xx, acc[i][1]);
            xx = dup2(xv.w);
            acc[i][0] = fma2(w3.x, xx, acc[i][0]); acc[i][1] = fma2(w3.y, xx, acc[i][1]);
        }
    }

#pragma unroll
    for (int i = 0; i < 8; i++) {
        int gr = row0 + wid * 8 + i;
        if (gr < NN) {
            float4 o;
            o.x = lo2(acc[i][0]); o.y = hi2(acc[i][0]);
            o.z = lo2(acc[i][1]); o.w = hi2(acc[i][1]);
            ((float4*)(g_ft + (size_t)gr * D))[lane] = o;
        }
    }
}

// fused per-node score + online softmax + aggregation: warp per dst node.
// dest + edot resolved IN DEVICE CODE (host-side &g_feat is garbage).
__global__ void __launch_bounds__(256) k_node_fused(
    float* __restrict__ dest_ext, int to_internal, int layer)
{
    int n = (blockIdx.x * 256 + threadIdx.x) >> 5;
    int lane = threadIdx.x & 31;
    if (n >= NN) return;
    float* dest = to_internal ? g_feat : dest_ext;
    const float* edot = g_edot + (size_t)layer * NE;
    int off = g_cnt[n], end = g_cnt[n + 1];
    float sdn = g_sdst[n];

    // pass 1: score + online max/denominator
    float m = -1e30f, den = 0.f;
    for (int j = off + lane; j < end; j += 32) {
        int s = g_ssorted[j];
        float sc = g_ssrc[s] + sdn + edot[j];
        g_sc2[j] = sc;
        if (sc > m) { den = den * __expf(m - sc) + 1.f; m = sc; }
        else den += __expf(sc - m);
    }
#pragma unroll
    for (int o = 16; o; o >>= 1) {
        float mo = __shfl_xor_sync(0xffffffffu, m, o);
        float dn = __shfl_xor_sync(0xffffffffu, den, o);
        float mn = fmaxf(m, mo);
        den = den * __expf(m - mn) + dn * __expf(mo - mn);
        m = mn;
    }
    float inv_den = den > 0.f ? __fdividef(1.f, den) : 0.f;

    // pass 2: aggregate (2-deep pipelined gather, packed fma2)
    unsigned long long acc0 = 0ull, acc1 = 0ull;
    for (int jb = off; jb < end; jb += 32) {
        int j = jb + lane;
        float al = 0.f; int sv = 0;
        if (j < end) {
            sv = g_ssorted[j];
            al = __expf(g_sc2[j] - m) * inv_den;
        }
        int cnt = min(32, end - jb);
        int k = 0;
        for (; k + 2 <= cnt; k += 2) {
            float a0f = __shfl_sync(0xffffffffu, al, k);
            float a1f = __shfl_sync(0xffffffffu, al, k + 1);
            int s0 = __shfl_sync(0xffffffffu, sv, k);
            int s1 = __shfl_sync(0xffffffffu, sv, k + 1);
            ulonglong2 v0 = ((const ulonglong2*)(g_ft + (size_t)s0 * D))[lane];
            ulonglong2 v1 = ((const ulonglong2*)(g_ft + (size_t)s1 * D))[lane];
            unsigned long long aa0 = dup2(a0f), aa1 = dup2(a1f);
            acc0 = fma2(v0.x, aa0, acc0); acc1 = fma2(v0.y, aa0, acc1);
            acc0 = fma2(v1.x, aa1, acc0); acc1 = fma2(v1.y, aa1, acc1);
        }
        if (k < cnt) {
            float a0f = __shfl_sync(0xffffffffu, al, k);
            int s0 = __shfl_sync(0xffffffffu, sv, k);
            ulonglong2 v0 = ((const ulonglong2*)(g_ft + (size_t)s0 * D))[lane];
            unsigned long long aa0 = dup2(a0f);
            acc0 = fma2(v0.x, aa0, acc0); acc1 = fma2(v0.y, aa0, acc1);
        }
    }
    float4 o;
    o.x = lo2(acc0); o.y = hi2(acc0); o.z = lo2(acc1); o.w = hi2(acc1);
    o.x = o.x >= 0.f ? o.x : 0.01f * o.x;
    o.y = o.y >= 0.f ? o.y : 0.01f * o.y;
    o.z = o.z >= 0.f ? o.z : 0.01f * o.z;
    o.w = o.w >= 0.f ? o.w : 0.01f * o.w;
    ((float4*)(dest + (size_t)n * D))[lane] = o;
}

// ---------------- launch ----------------
extern "C" void kernel_launch(void* const* d_in, const int* in_sizes, int n_in,
                              void* d_out, int out_size)
{
    const int*   src     = (const int*)  d_in[0];
    const int*   dst     = (const int*)  d_in[1];
    const float* n_feats = (const float*)d_in[2];
    const float* e_feats = (const float*)d_in[3];
    const float* W0      = (const float*)d_in[4];
    const float* Wih     = (const float*)d_in[5];
    const float* Whh     = (const float*)d_in[6];
    const float* bih     = (const float*)d_in[7];
    const float* bhh     = (const float*)d_in[8];
    const float* a_w     = (const float*)d_in[9];

    int n_edges = in_sizes[0] / 3;        // 800000
    int n_nodes = in_sizes[2] / (3 * D);  // 50000

    int smem_rec  = 6 * 1024 * 16 + (128 + 512 + 512) * (int)sizeof(float);  // ~100.5KB
    int smem_gemm = (D * D + 64 * D + 2 * D) * (int)sizeof(float);           // ~97KB
    cudaFuncSetAttribute(k_lstm_rec, cudaFuncAttributeMaxDynamicSharedMemorySize, smem_rec);
    cudaFuncSetAttribute(k_gat_gemm, cudaFuncAttributeMaxDynamicSharedMemorySize, smem_gemm);

    // only timestep j=2 matters for the output (feats never mix across j)
    const int*   src2 = src + 2 * n_edges;
    const int*   dst2 = dst + 2 * n_edges;
    const float* nf2  = n_feats + (size_t)2 * n_nodes * D;
    const float* ef2  = e_feats + (size_t)2 * n_edges * DE;

    // --- build dst-sorted edge structure + both layers' edge dots, once ---
    k_zero_cnt<<<(NN + 256) / 256, 256>>>();
    k_hist<<<(n_edges + 255) / 256, 256>>>(dst2);
    k_scan<<<1, 1024>>>();
    k_scatter<<<(n_edges + 255) / 256, 256>>>(src2, dst2, ef2, a_w);

    // --- LSTM chains for both layers (grid.y / grid.x = 2) ---
    k_transpose_wih<<<(2 * G4 * D + 255) / 256, 256>>>(Wih);
    for (int call = 0; call < 3; call++) {
        k_lstm_g0<<<dim3(D / 4, 2), 512>>>(W0, call > 0, bih, bhh);
        k_lstm_rec<<<2, 1024, smem_rec>>>(Whh);
    }

    // --- GAT layers (atomic-free, 2 kernels per layer) ---
    for (int layer = 0; layer < 2; layer++) {
        k_gat_gemm<<<(n_nodes + 63) / 64, 256, smem_gemm>>>(nf2, layer, a_w);
        k_node_fused<<<(n_nodes * 32 + 255) / 256, 256>>>((float*)d_out, layer == 0 ? 1 : 0, layer);
    }
}